// round 3
// baseline (speedup 1.0000x reference)
#include <cuda_runtime.h>
#include <math.h>
#include <stdint.h>

#define D 128
#define N_MAX 50176          // 1024 * 49 ceiling
#define E_MAX 800000
#define TILE_N 192
#define MLP_THREADS 384
#define SIN 196   // s_in row stride (floats)
#define SW  132   // s_w row stride

// Scratch (device globals — no allocation allowed)
__device__ int   g_degi[N_MAX];
__device__ int   g_off[N_MAX + 1];
__device__ int   g_cur[N_MAX];
__device__ int   g_csr[E_MAX];
__device__ float g_norm[N_MAX];
__device__ float g_agg[(size_t)N_MAX * D];

// ---------------------------------------------------------------------------
// packed f32x2 helpers (Blackwell sm_103a)
// ---------------------------------------------------------------------------
__device__ __forceinline__ unsigned long long pk2(float lo, float hi) {
    unsigned long long r;
    asm("mov.b64 %0, {%1, %2};" : "=l"(r) : "f"(lo), "f"(hi));
    return r;
}
__device__ __forceinline__ unsigned long long fma2(unsigned long long a,
                                                   unsigned long long b,
                                                   unsigned long long c) {
    unsigned long long d;
    asm("fma.rn.f32x2 %0, %1, %2, %3;" : "=l"(d) : "l"(a), "l"(b), "l"(c));
    return d;
}
__device__ __forceinline__ float2 upk2(unsigned long long v) {
    float2 f;
    asm("mov.b64 {%0, %1}, %2;" : "=f"(f.x), "=f"(f.y) : "l"(v));
    return f;
}

// ---------------------------------------------------------------------------
// 1) int in-degree histogram over dst
// ---------------------------------------------------------------------------
__global__ void deg_kernel(const int* __restrict__ dst, int E) {
    int i = blockIdx.x * blockDim.x + threadIdx.x;
    if (i < E) atomicAdd(&g_degi[dst[i]], 1);
}

// ---------------------------------------------------------------------------
// 2) single-block scan: offsets + cursors + norm
// ---------------------------------------------------------------------------
__global__ void scan_kernel(int N) {
    __shared__ int ssum[1024];
    const int t = threadIdx.x;
    const int CH = (N + 1023) >> 10;
    const int beg = t * CH;
    const int end = min(beg + CH, N);

    int s = 0;
    for (int i = beg; i < end; i++) s += g_degi[i];
    ssum[t] = s;
    __syncthreads();

    // Hillis-Steele inclusive scan
    for (int ofs = 1; ofs < 1024; ofs <<= 1) {
        int v = (t >= ofs) ? ssum[t - ofs] : 0;
        __syncthreads();
        ssum[t] += v;
        __syncthreads();
    }

    int run = (t == 0) ? 0 : ssum[t - 1];
    for (int i = beg; i < end; i++) {
        int d = g_degi[i];
        g_off[i] = run;
        g_cur[i] = run;
        g_norm[i] = rsqrtf(fmaxf((float)d, 1.0f));
        run += d;
    }
    if (t == 1023) g_off[N] = ssum[1023];
}

// ---------------------------------------------------------------------------
// 3) scatter edges into CSR (by dst), storing src ids
// ---------------------------------------------------------------------------
__global__ void scatter_kernel(const int* __restrict__ src,
                               const int* __restrict__ dst, int E) {
    int i = blockIdx.x * blockDim.x + threadIdx.x;
    if (i < E) {
        int d = dst[i];
        int pos = atomicAdd(&g_cur[d], 1);
        g_csr[pos] = src[i];
    }
}

// ---------------------------------------------------------------------------
// 4) segment reduce: one warp per dst node.
//    agg[n] = norm[n] * sum_{e in CSR[n]} x[src_e] * norm[src_e]
//    Writes agg exactly once (no float atomics, no agg memset needed).
// ---------------------------------------------------------------------------
__global__ void segreduce_kernel(const float* __restrict__ x, int N) {
    int w = (blockIdx.x * blockDim.x + threadIdx.x) >> 5;
    int lane = threadIdx.x & 31;
    if (w >= N) return;

    const int beg = g_off[w];
    const int end = g_off[w + 1];
    const float4* x4 = (const float4*)x;

    float4 acc = make_float4(0.f, 0.f, 0.f, 0.f);
    int e = beg;
    // 2-wide software pipeline to expose load parallelism
    for (; e + 2 <= end; e += 2) {
        int s0 = __ldg(&g_csr[e]);
        int s1 = __ldg(&g_csr[e + 1]);
        float n0 = __ldg(&g_norm[s0]);
        float n1 = __ldg(&g_norm[s1]);
        float4 v0 = __ldg(&x4[(size_t)s0 * 32 + lane]);
        float4 v1 = __ldg(&x4[(size_t)s1 * 32 + lane]);
        acc.x = fmaf(v0.x, n0, acc.x); acc.y = fmaf(v0.y, n0, acc.y);
        acc.z = fmaf(v0.z, n0, acc.z); acc.w = fmaf(v0.w, n0, acc.w);
        acc.x = fmaf(v1.x, n1, acc.x); acc.y = fmaf(v1.y, n1, acc.y);
        acc.z = fmaf(v1.z, n1, acc.z); acc.w = fmaf(v1.w, n1, acc.w);
    }
    if (e < end) {
        int s0 = __ldg(&g_csr[e]);
        float n0 = __ldg(&g_norm[s0]);
        float4 v0 = __ldg(&x4[(size_t)s0 * 32 + lane]);
        acc.x = fmaf(v0.x, n0, acc.x); acc.y = fmaf(v0.y, n0, acc.y);
        acc.z = fmaf(v0.z, n0, acc.z); acc.w = fmaf(v0.w, n0, acc.w);
    }

    float nd = g_norm[w];
    acc.x *= nd; acc.y *= nd; acc.z *= nd; acc.w *= nd;
    ((float4*)g_agg)[(size_t)w * 32 + lane] = acc;
}

// ---------------------------------------------------------------------------
// 5) Fused 2-layer MLP with packed f32x2 FMAs (unchanged tiling; agg is
//    already fully normalized, so the fill is a plain copy).
// ---------------------------------------------------------------------------
__global__ void __launch_bounds__(MLP_THREADS, 1)
mlp_kernel(const float* __restrict__ wc, const float* __restrict__ bc,
           const float* __restrict__ wl, const float* __restrict__ bl,
           float* __restrict__ out, int N) {
    extern __shared__ float sm[];
    float* s_in = sm;                  // [128][SIN]  ([k][n]) ; later s_h [n][128]
    float* s_w  = sm + 128 * SIN;      // [128][SW]   ([k][o])

    const int tid = threadIdx.x;
    const int n0 = blockIdx.x * TILE_N;
    const int tx = tid & 15;    // o-group
    const int ty = tid >> 4;    // n-group (0..23)

    for (int i = tid; i < 128 * 128; i += MLP_THREADS) {
        int o = i >> 7, k = i & 127;
        s_w[k * SW + o] = wc[i];
    }
    for (int i = tid; i < TILE_N * 128; i += MLP_THREADS) {
        int n = i >> 7, k = i & 127;
        int gn = n0 + n;
        float v = 0.0f;
        if (gn < N) v = g_agg[(size_t)gn * 128 + k];
        s_in[k * SIN + n] = v;
    }
    __syncthreads();

    unsigned long long acc[8][4];

    // ================= GEMM 1 =================
    #pragma unroll
    for (int i = 0; i < 8; i++)
        #pragma unroll
        for (int j = 0; j < 4; j++) acc[i][j] = 0ull;

    #pragma unroll 2
    for (int k = 0; k < 128; k++) {
        float4 a0 = *(const float4*)&s_in[k * SIN + ty * 8];
        float4 a1 = *(const float4*)&s_in[k * SIN + ty * 8 + 4];
        float4 b0 = *(const float4*)&s_w[k * SW + tx * 8];
        float4 b1 = *(const float4*)&s_w[k * SW + tx * 8 + 4];
        unsigned long long bp[4] = {pk2(b0.x, b0.y), pk2(b0.z, b0.w),
                                    pk2(b1.x, b1.y), pk2(b1.z, b1.w)};
        float a[8] = {a0.x, a0.y, a0.z, a0.w, a1.x, a1.y, a1.z, a1.w};
        #pragma unroll
        for (int i = 0; i < 8; i++) {
            unsigned long long ap = pk2(a[i], a[i]);
            #pragma unroll
            for (int j = 0; j < 4; j++) acc[i][j] = fma2(ap, bp[j], acc[i][j]);
        }
    }

    __syncthreads();

    // ---- h1 = relu(acc + bc), stage as s_h[n][o]; also load w2 ----
    float* s_h = s_in;  // [TILE_N][128]
    {
        float4 bb0 = *(const float4*)&bc[tx * 8];
        float4 bb1 = *(const float4*)&bc[tx * 8 + 4];
        float bias[8] = {bb0.x, bb0.y, bb0.z, bb0.w, bb1.x, bb1.y, bb1.z, bb1.w};
        #pragma unroll
        for (int i = 0; i < 8; i++) {
            float h[8];
            #pragma unroll
            for (int j = 0; j < 4; j++) {
                float2 v = upk2(acc[i][j]);
                h[2 * j]     = fmaxf(v.x + bias[2 * j], 0.0f);
                h[2 * j + 1] = fmaxf(v.y + bias[2 * j + 1], 0.0f);
            }
            float* p = &s_h[(ty * 8 + i) * 128 + tx * 8];
            *(float4*)p       = make_float4(h[0], h[1], h[2], h[3]);
            *(float4*)(p + 4) = make_float4(h[4], h[5], h[6], h[7]);
        }
    }
    for (int i = tid; i < 128 * 128; i += MLP_THREADS) {
        int o = i >> 7, k = i & 127;
        s_w[k * SW + o] = wl[i];
    }
    __syncthreads();

    // ================= GEMM 2 =================
    #pragma unroll
    for (int i = 0; i < 8; i++)
        #pragma unroll
        for (int j = 0; j < 4; j++) acc[i][j] = 0ull;

    for (int k = 0; k < 128; k += 4) {
        float4 av[8];
        #pragma unroll
        for (int i = 0; i < 8; i++)
            av[i] = *(const float4*)&s_h[(ty * 8 + i) * 128 + k];
        #pragma unroll
        for (int kk = 0; kk < 4; kk++) {
            float4 b0 = *(const float4*)&s_w[(k + kk) * SW + tx * 8];
            float4 b1 = *(const float4*)&s_w[(k + kk) * SW + tx * 8 + 4];
            unsigned long long bp[4] = {pk2(b0.x, b0.y), pk2(b0.z, b0.w),
                                        pk2(b1.x, b1.y), pk2(b1.z, b1.w)};
            #pragma unroll
            for (int i = 0; i < 8; i++) {
                float a = (kk == 0) ? av[i].x : (kk == 1) ? av[i].y
                         : (kk == 2) ? av[i].z : av[i].w;
                unsigned long long ap = pk2(a, a);
                #pragma unroll
                for (int j = 0; j < 4; j++) acc[i][j] = fma2(ap, bp[j], acc[i][j]);
            }
        }
    }

    // ---- relu(acc + bl) -> gmem ----
    {
        float4 bb0 = *(const float4*)&bl[tx * 8];
        float4 bb1 = *(const float4*)&bl[tx * 8 + 4];
        float bias[8] = {bb0.x, bb0.y, bb0.z, bb0.w, bb1.x, bb1.y, bb1.z, bb1.w};
        #pragma unroll
        for (int i = 0; i < 8; i++) {
            int gn = n0 + ty * 8 + i;
            if (gn < N) {
                float h[8];
                #pragma unroll
                for (int j = 0; j < 4; j++) {
                    float2 v = upk2(acc[i][j]);
                    h[2 * j]     = fmaxf(v.x + bias[2 * j], 0.0f);
                    h[2 * j + 1] = fmaxf(v.y + bias[2 * j + 1], 0.0f);
                }
                float* p = &out[(size_t)gn * 128 + tx * 8];
                *(float4*)p       = make_float4(h[0], h[1], h[2], h[3]);
                *(float4*)(p + 4) = make_float4(h[4], h[5], h[6], h[7]);
            }
        }
    }
}

// ---------------------------------------------------------------------------
extern "C" void kernel_launch(void* const* d_in, const int* in_sizes, int n_in,
                              void* d_out, int out_size) {
    const float* x    = (const float*)d_in[0];
    const int*   src  = (const int*)  d_in[1];
    const int*   dst  = (const int*)  d_in[2];
    const float* wc   = (const float*)d_in[3];
    const float* bc   = (const float*)d_in[4];
    const float* wl   = (const float*)d_in[5];
    const float* bl   = (const float*)d_in[6];
    float* out = (float*)d_out;

    const int N = in_sizes[0] / D;
    const int E = in_sizes[1];

    void* p_degi = nullptr;
    cudaGetSymbolAddress(&p_degi, g_degi);
    cudaMemsetAsync(p_degi, 0, (size_t)N * sizeof(int));

    deg_kernel<<<(E + 255) / 256, 256>>>(dst, E);
    scan_kernel<<<1, 1024>>>(N);
    scatter_kernel<<<(E + 255) / 256, 256>>>(src, dst, E);

    long long sr_threads = (long long)N * 32;
    int sr_blocks = (int)((sr_threads + 255) / 256);
    segreduce_kernel<<<sr_blocks, 256>>>(x, N);

    const int smem_bytes = (128 * SIN + 128 * SW) * sizeof(float);
    cudaFuncSetAttribute(mlp_kernel, cudaFuncAttributeMaxDynamicSharedMemorySize, smem_bytes);
    int mlp_blocks = (N + TILE_N - 1) / TILE_N;
    mlp_kernel<<<mlp_blocks, MLP_THREADS, smem_bytes>>>(wc, bc, wl, bl, out, N);
}

// round 4
// speedup vs baseline: 1.1686x; 1.1686x over previous
#include <cuda_runtime.h>
#include <math.h>
#include <stdint.h>

#define D 128
#define N_MAX 50048
#define TILE_N 256
#define MLP_THREADS 512
#define SIN 260   // s_in row stride (floats), mult of 4
#define SW  132   // s_w row stride (floats), mult of 4

// Scratch (device globals — no allocation allowed)
__device__ float g_deg[N_MAX];
__device__ float g_norm[N_MAX];
__device__ float g_agg[(size_t)N_MAX * D];

// ---------------------------------------------------------------------------
// packed f32x2 helpers (Blackwell sm_103a)
// ---------------------------------------------------------------------------
__device__ __forceinline__ unsigned long long pk2(float lo, float hi) {
    unsigned long long r;
    asm("mov.b64 %0, {%1, %2};" : "=l"(r) : "f"(lo), "f"(hi));
    return r;
}
__device__ __forceinline__ unsigned long long fma2(unsigned long long a,
                                                   unsigned long long b,
                                                   unsigned long long c) {
    unsigned long long d;
    asm("fma.rn.f32x2 %0, %1, %2, %3;" : "=l"(d) : "l"(a), "l"(b), "l"(c));
    return d;
}
__device__ __forceinline__ float2 upk2(unsigned long long v) {
    float2 f;
    asm("mov.b64 {%0, %1}, %2;" : "=f"(f.x), "=f"(f.y) : "l"(v));
    return f;
}

// ---------------------------------------------------------------------------
// 1) in-degree count over dst
// ---------------------------------------------------------------------------
__global__ void deg_kernel(const int* __restrict__ dst, int E) {
    int i = blockIdx.x * blockDim.x + threadIdx.x;
    if (i < E) atomicAdd(&g_deg[dst[i]], 1.0f);
}

// ---------------------------------------------------------------------------
// 2) norm = rsqrt(max(deg,1))
// ---------------------------------------------------------------------------
__global__ void norm_kernel(int N) {
    int i = blockIdx.x * blockDim.x + threadIdx.x;
    if (i < N) g_norm[i] = rsqrtf(fmaxf(g_deg[i], 1.0f));
}

// ---------------------------------------------------------------------------
// 3) SPMM: agg[dst] += x[src] * norm[src]  (one warp per edge, red.v4 scatter)
// ---------------------------------------------------------------------------
__global__ void spmm_kernel(const float* __restrict__ x,
                            const int* __restrict__ src,
                            const int* __restrict__ dst,
                            int E) {
    int t = blockIdx.x * blockDim.x + threadIdx.x;
    int e = t >> 5;
    int lane = t & 31;
    if (e >= E) return;
    int s = __ldg(&src[e]);
    int d = __ldg(&dst[e]);
    float ns = __ldg((const float*)&g_norm[s]);
    float4 v = __ldg(((const float4*)(x + (size_t)s * D)) + lane);
    v.x *= ns; v.y *= ns; v.z *= ns; v.w *= ns;
    float* p = &g_agg[(size_t)d * D + lane * 4];
    asm volatile("red.global.add.v4.f32 [%0], {%1, %2, %3, %4};"
                 :: "l"(p), "f"(v.x), "f"(v.y), "f"(v.z), "f"(v.w)
                 : "memory");
}

// ---------------------------------------------------------------------------
// 4) Fused 2-layer MLP, packed f32x2 FMAs.
//    512 threads; tile 256 nodes x 128 outs; thread tile 8x8.
//    tx = tid&15 (o-group), ty = tid>>4 (n-group, 0..31).
// ---------------------------------------------------------------------------
__global__ void __launch_bounds__(MLP_THREADS, 1)
mlp_kernel(const float* __restrict__ wc, const float* __restrict__ bc,
           const float* __restrict__ wl, const float* __restrict__ bl,
           float* __restrict__ out, int N) {
    extern __shared__ float sm[];
    float* s_in = sm;                  // [128][SIN]  ([k][n]) ; later s_h [n][128]
    float* s_w  = sm + 128 * SIN;      // [128][SW]   ([k][o])

    const int tid = threadIdx.x;
    const int n0 = blockIdx.x * TILE_N;
    const int tx = tid & 15;    // o-group
    const int ty = tid >> 4;    // n-group (0..31)

    // ---- load w1 transposed ([o][k] -> [k][o]) ----
    for (int i = tid; i < 128 * 128; i += MLP_THREADS) {
        int o = i >> 7, k = i & 127;
        s_w[k * SW + o] = wc[i];
    }
    // ---- input tile * norm[dst], transposed to [k][n] (coalesced gmem) ----
    for (int i = tid; i < TILE_N * 128; i += MLP_THREADS) {
        int n = i >> 7, k = i & 127;
        int gn = n0 + n;
        float v = 0.0f;
        if (gn < N) v = g_agg[(size_t)gn * 128 + k] * g_norm[gn];
        s_in[k * SIN + n] = v;
    }
    __syncthreads();

    unsigned long long acc[8][4];

    // ================= GEMM 1 =================
    #pragma unroll
    for (int i = 0; i < 8; i++)
        #pragma unroll
        for (int j = 0; j < 4; j++) acc[i][j] = 0ull;

    #pragma unroll 2
    for (int k = 0; k < 128; k++) {
        float4 a0 = *(const float4*)&s_in[k * SIN + ty * 8];
        float4 a1 = *(const float4*)&s_in[k * SIN + ty * 8 + 4];
        // b pairs come straight out of shared memory as 64-bit lanes
        ulonglong2 bq0 = *(const ulonglong2*)&s_w[k * SW + tx * 8];
        ulonglong2 bq1 = *(const ulonglong2*)&s_w[k * SW + tx * 8 + 4];
        unsigned long long bp[4] = {bq0.x, bq0.y, bq1.x, bq1.y};
        float a[8] = {a0.x, a0.y, a0.z, a0.w, a1.x, a1.y, a1.z, a1.w};
        #pragma unroll
        for (int i = 0; i < 8; i++) {
            unsigned long long ap = pk2(a[i], a[i]);
            #pragma unroll
            for (int j = 0; j < 4; j++) acc[i][j] = fma2(ap, bp[j], acc[i][j]);
        }
    }

    __syncthreads();  // all GEMM1 reads of s_in / s_w complete

    // ---- h1 = relu(acc + bc), stage as s_h[n][o]; then load w2 ----
    float* s_h = s_in;  // [TILE_N][128]
    {
        float4 bb0 = *(const float4*)&bc[tx * 8];
        float4 bb1 = *(const float4*)&bc[tx * 8 + 4];
        float bias[8] = {bb0.x, bb0.y, bb0.z, bb0.w, bb1.x, bb1.y, bb1.z, bb1.w};
        #pragma unroll
        for (int i = 0; i < 8; i++) {
            float h[8];
            #pragma unroll
            for (int j = 0; j < 4; j++) {
                float2 v = upk2(acc[i][j]);
                h[2 * j]     = fmaxf(v.x + bias[2 * j], 0.0f);
                h[2 * j + 1] = fmaxf(v.y + bias[2 * j + 1], 0.0f);
            }
            float* p = &s_h[(ty * 8 + i) * 128 + tx * 8];
            *(float4*)p       = make_float4(h[0], h[1], h[2], h[3]);
            *(float4*)(p + 4) = make_float4(h[4], h[5], h[6], h[7]);
        }
    }
    for (int i = tid; i < 128 * 128; i += MLP_THREADS) {
        int o = i >> 7, k = i & 127;
        s_w[k * SW + o] = wl[i];
    }
    __syncthreads();

    // ================= GEMM 2 =================
    #pragma unroll
    for (int i = 0; i < 8; i++)
        #pragma unroll
        for (int j = 0; j < 4; j++) acc[i][j] = 0ull;

    for (int k = 0; k < 128; k += 4) {
        float4 av[8];
        #pragma unroll
        for (int i = 0; i < 8; i++)
            av[i] = *(const float4*)&s_h[(ty * 8 + i) * 128 + k];
        #pragma unroll
        for (int kk = 0; kk < 4; kk++) {
            ulonglong2 bq0 = *(const ulonglong2*)&s_w[(k + kk) * SW + tx * 8];
            ulonglong2 bq1 = *(const ulonglong2*)&s_w[(k + kk) * SW + tx * 8 + 4];
            unsigned long long bp[4] = {bq0.x, bq0.y, bq1.x, bq1.y};
            #pragma unroll
            for (int i = 0; i < 8; i++) {
                float a = (kk == 0) ? av[i].x : (kk == 1) ? av[i].y
                         : (kk == 2) ? av[i].z : av[i].w;
                unsigned long long ap = pk2(a, a);
                #pragma unroll
                for (int j = 0; j < 4; j++) acc[i][j] = fma2(ap, bp[j], acc[i][j]);
            }
        }
    }

    // ---- relu(acc + bl) -> gmem ----
    {
        float4 bb0 = *(const float4*)&bl[tx * 8];
        float4 bb1 = *(const float4*)&bl[tx * 8 + 4];
        float bias[8] = {bb0.x, bb0.y, bb0.z, bb0.w, bb1.x, bb1.y, bb1.z, bb1.w};
        #pragma unroll
        for (int i = 0; i < 8; i++) {
            int gn = n0 + ty * 8 + i;
            if (gn < N) {
                float h[8];
                #pragma unroll
                for (int j = 0; j < 4; j++) {
                    float2 v = upk2(acc[i][j]);
                    h[2 * j]     = fmaxf(v.x + bias[2 * j], 0.0f);
                    h[2 * j + 1] = fmaxf(v.y + bias[2 * j + 1], 0.0f);
                }
                float* p = &out[(size_t)gn * 128 + tx * 8];
                *(float4*)p       = make_float4(h[0], h[1], h[2], h[3]);
                *(float4*)(p + 4) = make_float4(h[4], h[5], h[6], h[7]);
            }
        }
    }
}

// ---------------------------------------------------------------------------
extern "C" void kernel_launch(void* const* d_in, const int* in_sizes, int n_in,
                              void* d_out, int out_size) {
    const float* x    = (const float*)d_in[0];
    const int*   src  = (const int*)  d_in[1];
    const int*   dst  = (const int*)  d_in[2];
    const float* wc   = (const float*)d_in[3];
    const float* bc   = (const float*)d_in[4];
    const float* wl   = (const float*)d_in[5];
    const float* bl   = (const float*)d_in[6];
    float* out = (float*)d_out;

    const int N = in_sizes[0] / D;
    const int E = in_sizes[1];

    void* p_deg = nullptr;
    void* p_agg = nullptr;
    cudaGetSymbolAddress(&p_deg, g_deg);
    cudaGetSymbolAddress(&p_agg, g_agg);
    cudaMemsetAsync(p_deg, 0, (size_t)N * sizeof(float));
    cudaMemsetAsync(p_agg, 0, (size_t)N * D * sizeof(float));

    deg_kernel<<<(E + 255) / 256, 256>>>(dst, E);
    norm_kernel<<<(N + 255) / 256, 256>>>(N);

    long long spmm_threads = (long long)E * 32;
    int spmm_blocks = (int)((spmm_threads + 255) / 256);
    spmm_kernel<<<spmm_blocks, 256>>>(x, src, dst, E);

    const int smem_bytes = (128 * SIN + 128 * SW) * sizeof(float);  // ~196KB
    cudaFuncSetAttribute(mlp_kernel, cudaFuncAttributeMaxDynamicSharedMemorySize, smem_bytes);
    int mlp_blocks = (N + TILE_N - 1) / TILE_N;
    mlp_kernel<<<mlp_blocks, MLP_THREADS, smem_bytes>>>(wc, bc, wl, bl, out, N);
}

// round 5
// speedup vs baseline: 1.2412x; 1.0621x over previous
#include <cuda_runtime.h>
#include <math.h>
#include <stdint.h>

#define D 128
#define N_MAX 50048
#define TILE_N 128
#define MLP_THREADS 256
#define SA 132   // s_in / s_h row stride (floats): banks 4r+c conflict-free
#define SB 136   // w_hi/w_lo row stride (floats): banks 8k+o conflict-free

// Scratch (device globals — no allocation allowed)
__device__ float g_deg[N_MAX];
__device__ float g_norm[N_MAX];
__device__ float g_agg[(size_t)N_MAX * D];

// ---------------------------------------------------------------------------
// tf32 helpers
// ---------------------------------------------------------------------------
__device__ __forceinline__ uint32_t f2tf32(float x) {
    uint32_t r;
    asm("cvt.rna.tf32.f32 %0, %1;" : "=r"(r) : "f"(x));
    return r;
}
__device__ __forceinline__ void mma_tf32(float d[4],
                                         uint32_t a0, uint32_t a1,
                                         uint32_t a2, uint32_t a3,
                                         uint32_t b0, uint32_t b1) {
    asm volatile(
        "mma.sync.aligned.m16n8k8.row.col.f32.tf32.tf32.f32 "
        "{%0,%1,%2,%3}, {%4,%5,%6,%7}, {%8,%9}, {%0,%1,%2,%3};"
        : "+f"(d[0]), "+f"(d[1]), "+f"(d[2]), "+f"(d[3])
        : "r"(a0), "r"(a1), "r"(a2), "r"(a3), "r"(b0), "r"(b1));
}

// ---------------------------------------------------------------------------
// 1) in-degree count over dst
// ---------------------------------------------------------------------------
__global__ void deg_kernel(const int* __restrict__ dst, int E) {
    int i = blockIdx.x * blockDim.x + threadIdx.x;
    if (i < E) atomicAdd(&g_deg[dst[i]], 1.0f);
}

// ---------------------------------------------------------------------------
// 2) norm = rsqrt(max(deg,1))
// ---------------------------------------------------------------------------
__global__ void norm_kernel(int N) {
    int i = blockIdx.x * blockDim.x + threadIdx.x;
    if (i < N) g_norm[i] = rsqrtf(fmaxf(g_deg[i], 1.0f));
}

// ---------------------------------------------------------------------------
// 3) SPMM: agg[dst] += x[src] * norm[src]  (one warp per edge, red.v4 scatter)
// ---------------------------------------------------------------------------
__global__ void spmm_kernel(const float* __restrict__ x,
                            const int* __restrict__ src,
                            const int* __restrict__ dst,
                            int E) {
    int t = blockIdx.x * blockDim.x + threadIdx.x;
    int e = t >> 5;
    int lane = t & 31;
    if (e >= E) return;
    int s = __ldg(&src[e]);
    int d = __ldg(&dst[e]);
    float ns = __ldg((const float*)&g_norm[s]);
    float4 v = __ldg(((const float4*)(x + (size_t)s * D)) + lane);
    v.x *= ns; v.y *= ns; v.z *= ns; v.w *= ns;
    float* p = &g_agg[(size_t)d * D + lane * 4];
    asm volatile("red.global.add.v4.f32 [%0], {%1, %2, %3, %4};"
                 :: "l"(p), "f"(v.x), "f"(v.y), "f"(v.z), "f"(v.w)
                 : "memory");
}

// ---------------------------------------------------------------------------
// 3xTF32 GEMM mainloop: d[mi][ni][] += s_a(128xK f32) @ (whi+wlo)(Kx128)
//   A split hi/lo in registers; B pre-split hi/lo in smem.
//   Warp grid 2(m) x 4(n); warp tile 64x32; frags m16n8k8.
// ---------------------------------------------------------------------------
__device__ __forceinline__ void gemm_3xtf32(const float* __restrict__ s_a,
                                            const float* __restrict__ s_bhi,
                                            const float* __restrict__ s_blo,
                                            float d[4][4][4],
                                            int lane, int warp_m, int warp_n) {
    const int grp = lane >> 2;   // 0..7
    const int thr = lane & 3;    // 0..3

    #pragma unroll 4
    for (int k0 = 0; k0 < 128; k0 += 8) {
        // ---- B fragments (hi & lo) ----
        uint32_t bh[4][2], bl[4][2];
        #pragma unroll
        for (int ni = 0; ni < 4; ni++) {
            int o = warp_n * 32 + ni * 8 + grp;
            int r0 = (k0 + thr) * SB + o;
            int r1 = (k0 + thr + 4) * SB + o;
            bh[ni][0] = __float_as_uint(s_bhi[r0]);
            bh[ni][1] = __float_as_uint(s_bhi[r1]);
            bl[ni][0] = __float_as_uint(s_blo[r0]);
            bl[ni][1] = __float_as_uint(s_blo[r1]);
        }
        // ---- A fragments: load f32, split hi/lo ----
        #pragma unroll
        for (int mi = 0; mi < 4; mi++) {
            const float* pa = s_a + (warp_m * 64 + mi * 16 + grp) * SA + k0 + thr;
            float a0f = pa[0];
            float a1f = pa[8 * SA];
            float a2f = pa[4];
            float a3f = pa[8 * SA + 4];
            uint32_t ah0 = f2tf32(a0f), ah1 = f2tf32(a1f);
            uint32_t ah2 = f2tf32(a2f), ah3 = f2tf32(a3f);
            uint32_t al0 = f2tf32(a0f - __uint_as_float(ah0));
            uint32_t al1 = f2tf32(a1f - __uint_as_float(ah1));
            uint32_t al2 = f2tf32(a2f - __uint_as_float(ah2));
            uint32_t al3 = f2tf32(a3f - __uint_as_float(ah3));
            #pragma unroll
            for (int ni = 0; ni < 4; ni++) {
                mma_tf32(d[mi][ni], ah0, ah1, ah2, ah3, bh[ni][0], bh[ni][1]);
                mma_tf32(d[mi][ni], ah0, ah1, ah2, ah3, bl[ni][0], bl[ni][1]);
                mma_tf32(d[mi][ni], al0, al1, al2, al3, bh[ni][0], bh[ni][1]);
            }
        }
    }
}

// ---------------------------------------------------------------------------
// 4) Fused 2-layer MLP on tensor cores (3xTF32).
// ---------------------------------------------------------------------------
__global__ void __launch_bounds__(MLP_THREADS, 1)
mlp_kernel(const float* __restrict__ wc, const float* __restrict__ bc,
           const float* __restrict__ wl, const float* __restrict__ bl,
           float* __restrict__ out, int N) {
    extern __shared__ float sm[];
    float* s_in  = sm;                           // [128][SA]  rows=node, cols=k
    float* s_whi = sm + 128 * SA;                // [128][SB]  rows=k, cols=o
    float* s_wlo = s_whi + 128 * SB;             // [128][SB]

    const int tid = threadIdx.x;
    const int lane = tid & 31;
    const int wid = tid >> 5;
    const int warp_m = wid >> 2;   // 0..1
    const int warp_n = wid & 3;    // 0..3
    const int n0 = blockIdx.x * TILE_N;
    const int grp = lane >> 2;
    const int thr = lane & 3;

    // ---- fill: w1 split hi/lo into [k][o]; input tile into [n][k] ----
    for (int i = tid; i < 128 * 128; i += MLP_THREADS) {
        int o = i >> 7, k = i & 127;
        float w = wc[i];
        uint32_t hi = f2tf32(w);
        s_whi[k * SB + o] = __uint_as_float(hi);
        s_wlo[k * SB + o] = __uint_as_float(f2tf32(w - __uint_as_float(hi)));
    }
    for (int i = tid; i < TILE_N * 128; i += MLP_THREADS) {
        int n = i >> 7, k = i & 127;
        int gn = n0 + n;
        float v = 0.0f;
        if (gn < N) v = g_agg[(size_t)gn * 128 + k] * g_norm[gn];
        s_in[n * SA + k] = v;
    }
    __syncthreads();

    float d[4][4][4];

    // ================= GEMM 1 =================
    #pragma unroll
    for (int mi = 0; mi < 4; mi++)
        #pragma unroll
        for (int ni = 0; ni < 4; ni++)
            #pragma unroll
            for (int q = 0; q < 4; q++) d[mi][ni][q] = 0.0f;

    gemm_3xtf32(s_in, s_whi, s_wlo, d, lane, warp_m, warp_n);

    __syncthreads();   // all warps done reading s_in / weights

    // ---- epilogue 1: h = relu(d + bc) -> s_h ([n][k] layout, reuse s_in) ----
    {
        float2 bias[4];
        #pragma unroll
        for (int ni = 0; ni < 4; ni++) {
            int col = warp_n * 32 + ni * 8 + thr * 2;
            bias[ni] = make_float2(__ldg(&bc[col]), __ldg(&bc[col + 1]));
        }
        #pragma unroll
        for (int mi = 0; mi < 4; mi++) {
            int row0 = warp_m * 64 + mi * 16 + grp;
            #pragma unroll
            for (int ni = 0; ni < 4; ni++) {
                int col = warp_n * 32 + ni * 8 + thr * 2;
                float2 v0 = make_float2(fmaxf(d[mi][ni][0] + bias[ni].x, 0.0f),
                                        fmaxf(d[mi][ni][1] + bias[ni].y, 0.0f));
                float2 v1 = make_float2(fmaxf(d[mi][ni][2] + bias[ni].x, 0.0f),
                                        fmaxf(d[mi][ni][3] + bias[ni].y, 0.0f));
                *(float2*)&s_in[row0 * SA + col]       = v0;
                *(float2*)&s_in[(row0 + 8) * SA + col] = v1;
            }
        }
    }
    // ---- fill w2 split hi/lo ----
    for (int i = tid; i < 128 * 128; i += MLP_THREADS) {
        int o = i >> 7, k = i & 127;
        float w = wl[i];
        uint32_t hi = f2tf32(w);
        s_whi[k * SB + o] = __uint_as_float(hi);
        s_wlo[k * SB + o] = __uint_as_float(f2tf32(w - __uint_as_float(hi)));
    }
    __syncthreads();

    // ================= GEMM 2 =================
    #pragma unroll
    for (int mi = 0; mi < 4; mi++)
        #pragma unroll
        for (int ni = 0; ni < 4; ni++)
            #pragma unroll
            for (int q = 0; q < 4; q++) d[mi][ni][q] = 0.0f;

    gemm_3xtf32(s_in, s_whi, s_wlo, d, lane, warp_m, warp_n);

    // ---- epilogue 2: out = relu(d + bl) -> gmem ----
    {
        float2 bias[4];
        #pragma unroll
        for (int ni = 0; ni < 4; ni++) {
            int col = warp_n * 32 + ni * 8 + thr * 2;
            bias[ni] = make_float2(__ldg(&bl[col]), __ldg(&bl[col + 1]));
        }
        #pragma unroll
        for (int mi = 0; mi < 4; mi++) {
            int row0 = warp_m * 64 + mi * 16 + grp;
            #pragma unroll
            for (int ni = 0; ni < 4; ni++) {
                int col = warp_n * 32 + ni * 8 + thr * 2;
                int gn0 = n0 + row0;
                int gn1 = gn0 + 8;
                if (gn0 < N) {
                    float2 v = make_float2(fmaxf(d[mi][ni][0] + bias[ni].x, 0.0f),
                                           fmaxf(d[mi][ni][1] + bias[ni].y, 0.0f));
                    *(float2*)&out[(size_t)gn0 * 128 + col] = v;
                }
                if (gn1 < N) {
                    float2 v = make_float2(fmaxf(d[mi][ni][2] + bias[ni].x, 0.0f),
                                           fmaxf(d[mi][ni][3] + bias[ni].y, 0.0f));
                    *(float2*)&out[(size_t)gn1 * 128 + col] = v;
                }
            }
        }
    }
}

// ---------------------------------------------------------------------------
extern "C" void kernel_launch(void* const* d_in, const int* in_sizes, int n_in,
                              void* d_out, int out_size) {
    const float* x    = (const float*)d_in[0];
    const int*   src  = (const int*)  d_in[1];
    const int*   dst  = (const int*)  d_in[2];
    const float* wc   = (const float*)d_in[3];
    const float* bc   = (const float*)d_in[4];
    const float* wl   = (const float*)d_in[5];
    const float* bl   = (const float*)d_in[6];
    float* out = (float*)d_out;

    const int N = in_sizes[0] / D;
    const int E = in_sizes[1];

    void* p_deg = nullptr;
    void* p_agg = nullptr;
    cudaGetSymbolAddress(&p_deg, g_deg);
    cudaGetSymbolAddress(&p_agg, g_agg);
    cudaMemsetAsync(p_deg, 0, (size_t)N * sizeof(float));
    cudaMemsetAsync(p_agg, 0, (size_t)N * D * sizeof(float));

    deg_kernel<<<(E + 255) / 256, 256>>>(dst, E);
    norm_kernel<<<(N + 255) / 256, 256>>>(N);

    long long spmm_threads = (long long)E * 32;
    int spmm_blocks = (int)((spmm_threads + 255) / 256);
    spmm_kernel<<<spmm_blocks, 256>>>(x, src, dst, E);

    const int smem_bytes = (128 * SA + 2 * 128 * SB) * sizeof(float);  // ~202KB
    cudaFuncSetAttribute(mlp_kernel, cudaFuncAttributeMaxDynamicSharedMemorySize, smem_bytes);
    int mlp_blocks = (N + TILE_N - 1) / TILE_N;
    mlp_kernel<<<mlp_blocks, MLP_THREADS, smem_bytes>>>(wc, bc, wl, bl, out, N);
}

// round 6
// speedup vs baseline: 1.6559x; 1.3341x over previous
#include <cuda_runtime.h>
#include <cuda_bf16.h>
#include <math.h>
#include <stdint.h>

#define D 128
#define N_MAX 50048
#define TILE_N 128
#define MLP_THREADS 256
#define SAW 68   // smem row stride in 32-bit words (bank-conflict-free: 4g+q)

// Scratch (device globals — no allocation allowed)
__device__ float g_deg[N_MAX];
__device__ float g_norm[N_MAX];
__device__ float g_agg[(size_t)N_MAX * D];

// ---------------------------------------------------------------------------
// bf16x2 helpers
// ---------------------------------------------------------------------------
__device__ __forceinline__ uint32_t pack_bf16x2(float v_lo, float v_hi) {
    // element for even k in low 16 bits
    uint32_t r;
    asm("cvt.rn.bf16x2.f32 %0, %1, %2;" : "=r"(r) : "f"(v_hi), "f"(v_lo));
    return r;
}
// split two f32 into (hi bf16x2, lo bf16x2)
__device__ __forceinline__ void split2(float v0, float v1,
                                       uint32_t& hi, uint32_t& lo) {
    hi = pack_bf16x2(v0, v1);
    float h0 = __uint_as_float(hi << 16);
    float h1 = __uint_as_float(hi & 0xffff0000u);
    lo = pack_bf16x2(v0 - h0, v1 - h1);
}
__device__ __forceinline__ void mma_bf16(float d[4],
                                         uint32_t a0, uint32_t a1,
                                         uint32_t a2, uint32_t a3,
                                         uint32_t b0, uint32_t b1) {
    asm volatile(
        "mma.sync.aligned.m16n8k16.row.col.f32.bf16.bf16.f32 "
        "{%0,%1,%2,%3}, {%4,%5,%6,%7}, {%8,%9}, {%0,%1,%2,%3};"
        : "+f"(d[0]), "+f"(d[1]), "+f"(d[2]), "+f"(d[3])
        : "r"(a0), "r"(a1), "r"(a2), "r"(a3), "r"(b0), "r"(b1));
}

// ---------------------------------------------------------------------------
// 1) in-degree count over dst
// ---------------------------------------------------------------------------
__global__ void deg_kernel(const int* __restrict__ dst, int E) {
    int i = blockIdx.x * blockDim.x + threadIdx.x;
    if (i < E) atomicAdd(&g_deg[dst[i]], 1.0f);
}

// ---------------------------------------------------------------------------
// 2) norm = rsqrt(max(deg,1))
// ---------------------------------------------------------------------------
__global__ void norm_kernel(int N) {
    int i = blockIdx.x * blockDim.x + threadIdx.x;
    if (i < N) g_norm[i] = rsqrtf(fmaxf(g_deg[i], 1.0f));
}

// ---------------------------------------------------------------------------
// 3) SPMM: agg[dst] += x[src] * norm[src]  (one warp per edge, red.v4 scatter)
// ---------------------------------------------------------------------------
__global__ void spmm_kernel(const float* __restrict__ x,
                            const int* __restrict__ src,
                            const int* __restrict__ dst,
                            int E) {
    int t = blockIdx.x * blockDim.x + threadIdx.x;
    int e = t >> 5;
    int lane = t & 31;
    if (e >= E) return;
    int s = __ldg(&src[e]);
    int d = __ldg(&dst[e]);
    float ns = __ldg((const float*)&g_norm[s]);
    float4 v = __ldg(((const float4*)(x + (size_t)s * D)) + lane);
    v.x *= ns; v.y *= ns; v.z *= ns; v.w *= ns;
    float* p = &g_agg[(size_t)d * D + lane * 4];
    asm volatile("red.global.add.v4.f32 [%0], {%1, %2, %3, %4};"
                 :: "l"(p), "f"(v.x), "f"(v.y), "f"(v.z), "f"(v.w)
                 : "memory");
}

// ---------------------------------------------------------------------------
// bf16-split GEMM mainloop: pure LDS + HMMA, no conversions.
//   s_a*: [128 rows][SAW words]  word = (k, k+1) bf16x2
//   s_w*: [128 o   ][SAW words]  word = (k, k+1) bf16x2  (B, col-major frag)
//   warp grid 2(m) x 4(n); warp tile 64x32; frags m16n8k16; 3 terms/frag.
// ---------------------------------------------------------------------------
__device__ __forceinline__ void gemm_bf16x3(const uint32_t* __restrict__ s_ahi,
                                            const uint32_t* __restrict__ s_alo,
                                            const uint32_t* __restrict__ s_whi,
                                            const uint32_t* __restrict__ s_wlo,
                                            float d[4][4][4],
                                            int g, int q, int warp_m, int warp_n) {
    #pragma unroll 2
    for (int kb = 0; kb < 64; kb += 8) {    // 8 kpairs = k16 per step
        // ---- B fragments ----
        uint32_t bh[4][2], bl[4][2];
        #pragma unroll
        for (int ni = 0; ni < 4; ni++) {
            int o = warp_n * 32 + ni * 8 + g;
            int r0 = o * SAW + kb + q;
            bh[ni][0] = s_whi[r0];
            bh[ni][1] = s_whi[r0 + 4];
            bl[ni][0] = s_wlo[r0];
            bl[ni][1] = s_wlo[r0 + 4];
        }
        // ---- A fragments + mma ----
        #pragma unroll
        for (int mi = 0; mi < 4; mi++) {
            int row = warp_m * 64 + mi * 16 + g;
            int r0 = row * SAW + kb + q;
            int r1 = (row + 8) * SAW + kb + q;
            uint32_t ah0 = s_ahi[r0],     ah1 = s_ahi[r1];
            uint32_t ah2 = s_ahi[r0 + 4], ah3 = s_ahi[r1 + 4];
            uint32_t al0 = s_alo[r0],     al1 = s_alo[r1];
            uint32_t al2 = s_alo[r0 + 4], al3 = s_alo[r1 + 4];
            #pragma unroll
            for (int ni = 0; ni < 4; ni++) {
                mma_bf16(d[mi][ni], ah0, ah1, ah2, ah3, bh[ni][0], bh[ni][1]);
                mma_bf16(d[mi][ni], ah0, ah1, ah2, ah3, bl[ni][0], bl[ni][1]);
                mma_bf16(d[mi][ni], al0, al1, al2, al3, bh[ni][0], bh[ni][1]);
            }
        }
    }
}

// ---------------------------------------------------------------------------
// 4) Fused 2-layer MLP on tensor cores (bf16 2-way split, 3 terms).
// ---------------------------------------------------------------------------
__global__ void __launch_bounds__(MLP_THREADS, 1)
mlp_kernel(const float* __restrict__ wc, const float* __restrict__ bc,
           const float* __restrict__ wl, const float* __restrict__ bl,
           float* __restrict__ out, int N) {
    extern __shared__ uint32_t sm[];
    uint32_t* s_ahi = sm;                      // [128][SAW]
    uint32_t* s_alo = s_ahi + 128 * SAW;
    uint32_t* s_whi = s_alo + 128 * SAW;
    uint32_t* s_wlo = s_whi + 128 * SAW;

    const int tid = threadIdx.x;
    const int lane = tid & 31;
    const int wid = tid >> 5;
    const int warp_m = wid >> 2;   // 0..1
    const int warp_n = wid & 3;    // 0..3
    const int g = lane >> 2;       // 0..7
    const int q = lane & 3;        // 0..3
    const int n0 = blockIdx.x * TILE_N;

    // ---- fill w1: [o][kpair], split hi/lo (coalesced float2 reads) ----
    for (int i = tid; i < 128 * 64; i += MLP_THREADS) {
        int o = i >> 6, kp = i & 63;
        float2 w = *(const float2*)&wc[o * 128 + kp * 2];
        uint32_t hi, lo;
        split2(w.x, w.y, hi, lo);
        s_whi[o * SAW + kp] = hi;
        s_wlo[o * SAW + kp] = lo;
    }
    // ---- fill input tile: agg[n][k] * norm[n], split hi/lo ----
    for (int i = tid; i < TILE_N * 64; i += MLP_THREADS) {
        int n = i >> 6, kp = i & 63;
        int gn = n0 + n;
        float2 v = make_float2(0.f, 0.f);
        float nn = 0.f;
        if (gn < N) {
            v = *(const float2*)&g_agg[(size_t)gn * 128 + kp * 2];
            nn = g_norm[gn];
        }
        uint32_t hi, lo;
        split2(v.x * nn, v.y * nn, hi, lo);
        s_ahi[n * SAW + kp] = hi;
        s_alo[n * SAW + kp] = lo;
    }
    __syncthreads();

    float d[4][4][4];

    // ================= GEMM 1 =================
    #pragma unroll
    for (int mi = 0; mi < 4; mi++)
        #pragma unroll
        for (int ni = 0; ni < 4; ni++)
            #pragma unroll
            for (int p = 0; p < 4; p++) d[mi][ni][p] = 0.0f;

    gemm_bf16x3(s_ahi, s_alo, s_whi, s_wlo, d, g, q, warp_m, warp_n);

    __syncthreads();   // everyone done reading s_a / s_w

    // ---- epilogue 1: h = relu(d + bc), split & write back to s_a ----
    {
        #pragma unroll
        for (int ni = 0; ni < 4; ni++) {
            int col = warp_n * 32 + ni * 8 + q * 2;
            int kp = col >> 1;
            float2 b = *(const float2*)&bc[col];
            #pragma unroll
            for (int mi = 0; mi < 4; mi++) {
                int row = warp_m * 64 + mi * 16 + g;
                float h0 = fmaxf(d[mi][ni][0] + b.x, 0.0f);
                float h1 = fmaxf(d[mi][ni][1] + b.y, 0.0f);
                float h2 = fmaxf(d[mi][ni][2] + b.x, 0.0f);
                float h3 = fmaxf(d[mi][ni][3] + b.y, 0.0f);
                uint32_t hi, lo;
                split2(h0, h1, hi, lo);
                s_ahi[row * SAW + kp] = hi;
                s_alo[row * SAW + kp] = lo;
                split2(h2, h3, hi, lo);
                s_ahi[(row + 8) * SAW + kp] = hi;
                s_alo[(row + 8) * SAW + kp] = lo;
            }
        }
    }
    // ---- fill w2 split hi/lo ----
    for (int i = tid; i < 128 * 64; i += MLP_THREADS) {
        int o = i >> 6, kp = i & 63;
        float2 w = *(const float2*)&wl[o * 128 + kp * 2];
        uint32_t hi, lo;
        split2(w.x, w.y, hi, lo);
        s_whi[o * SAW + kp] = hi;
        s_wlo[o * SAW + kp] = lo;
    }
    __syncthreads();

    // ================= GEMM 2 =================
    #pragma unroll
    for (int mi = 0; mi < 4; mi++)
        #pragma unroll
        for (int ni = 0; ni < 4; ni++)
            #pragma unroll
            for (int p = 0; p < 4; p++) d[mi][ni][p] = 0.0f;

    gemm_bf16x3(s_ahi, s_alo, s_whi, s_wlo, d, g, q, warp_m, warp_n);

    // ---- epilogue 2: out = relu(d + bl) -> gmem ----
    {
        #pragma unroll
        for (int ni = 0; ni < 4; ni++) {
            int col = warp_n * 32 + ni * 8 + q * 2;
            float2 b = *(const float2*)&bl[col];
            #pragma unroll
            for (int mi = 0; mi < 4; mi++) {
                int row = warp_m * 64 + mi * 16 + g;
                int gn0 = n0 + row;
                int gn1 = gn0 + 8;
                if (gn0 < N) {
                    float2 v = make_float2(fmaxf(d[mi][ni][0] + b.x, 0.0f),
                                           fmaxf(d[mi][ni][1] + b.y, 0.0f));
                    *(float2*)&out[(size_t)gn0 * 128 + col] = v;
                }
                if (gn1 < N) {
                    float2 v = make_float2(fmaxf(d[mi][ni][2] + b.x, 0.0f),
                                           fmaxf(d[mi][ni][3] + b.y, 0.0f));
                    *(float2*)&out[(size_t)gn1 * 128 + col] = v;
                }
            }
        }
    }
}

// ---------------------------------------------------------------------------
extern "C" void kernel_launch(void* const* d_in, const int* in_sizes, int n_in,
                              void* d_out, int out_size) {
    const float* x    = (const float*)d_in[0];
    const int*   src  = (const int*)  d_in[1];
    const int*   dst  = (const int*)  d_in[2];
    const float* wc   = (const float*)d_in[3];
    const float* bc   = (const float*)d_in[4];
    const float* wl   = (const float*)d_in[5];
    const float* bl   = (const float*)d_in[6];
    float* out = (float*)d_out;

    const int N = in_sizes[0] / D;
    const int E = in_sizes[1];

    void* p_deg = nullptr;
    void* p_agg = nullptr;
    cudaGetSymbolAddress(&p_deg, g_deg);
    cudaGetSymbolAddress(&p_agg, g_agg);
    cudaMemsetAsync(p_deg, 0, (size_t)N * sizeof(float));
    cudaMemsetAsync(p_agg, 0, (size_t)N * D * sizeof(float));

    deg_kernel<<<(E + 255) / 256, 256>>>(dst, E);
    norm_kernel<<<(N + 255) / 256, 256>>>(N);

    long long spmm_threads = (long long)E * 32;
    int spmm_blocks = (int)((spmm_threads + 255) / 256);
    spmm_kernel<<<spmm_blocks, 256>>>(x, src, dst, E);

    const int smem_bytes = 4 * 128 * SAW * sizeof(uint32_t);  // ~136KB
    cudaFuncSetAttribute(mlp_kernel, cudaFuncAttributeMaxDynamicSharedMemorySize, smem_bytes);
    int mlp_blocks = (N + TILE_N - 1) / TILE_N;
    mlp_kernel<<<mlp_blocks, MLP_THREADS, smem_bytes>>>(wc, bc, wl, bl, out, N);
}